// round 1
// baseline (speedup 1.0000x reference)
#include <cuda_runtime.h>
#include <math.h>

#define NN 100000
#define NE 800000
#define C 128

// ---------------- scratch (device globals; no allocation allowed) ----------
__device__ float g_q[NN * C];
__device__ float g_k[NN * C];
__device__ float g_v[NN * C];
__device__ float g_skip[NN * C];
__device__ float g_h[NN * C];

__device__ int g_deg[NN];
__device__ int g_off[NN + 1];
__device__ int g_cursor[NN];
__device__ int g_csr[NE];
__device__ int g_bsum[64];
__device__ int g_boff[64];
__device__ int g_is64;

// ---------------- edge-index dtype detection -------------------------------
// Reference declares int64, but JAX without x64 silently emits int32.
// Interpreting int32 data as int64 yields values >= 2^32 almost surely
// (hi word is the next random index, nonzero w.p. ~1-1e-5 per element).
__global__ void k_detect(const void* ei) {
    if (blockIdx.x == 0 && threadIdx.x == 0) {
        const long long* p = (const long long*)ei;
        int ok = 1;
        for (int i = 0; i < 256; i++) {
            long long v = p[i];
            if (v < 0 || v >= NN) { ok = 0; break; }
        }
        g_is64 = ok;
    }
}

__device__ __forceinline__ int load_src(const void* ei, int e) {
    if (g_is64) return (int)((const long long*)ei)[e];
    return ((const int*)ei)[e];
}
__device__ __forceinline__ int load_dst(const void* ei, int e) {
    if (g_is64) return (int)((const long long*)ei)[NE + e];
    return ((const int*)ei)[NE + e];
}

// ---------------- CSR construction ------------------------------------------
__global__ void k_zero_deg() {
    int i = blockIdx.x * blockDim.x + threadIdx.x;
    if (i < NN) g_deg[i] = 0;
}

__global__ void k_hist(const void* ei) {
    int e = blockIdx.x * blockDim.x + threadIdx.x;
    if (e < NE) atomicAdd(&g_deg[load_dst(ei, e)], 1);
}

#define SCAN_ITEMS 8
#define SCAN_THREADS 256
#define SCAN_TILE (SCAN_ITEMS * SCAN_THREADS)
#define SCAN_NB ((NN + SCAN_TILE - 1) / SCAN_TILE)

__global__ void k_scan1() {
    __shared__ int ssum[SCAN_THREADS];
    int b = blockIdx.x, t = threadIdx.x;
    int base = b * SCAN_TILE + t * SCAN_ITEMS;
    int vals[SCAN_ITEMS];
    int s = 0;
#pragma unroll
    for (int i = 0; i < SCAN_ITEMS; i++) {
        int idx = base + i;
        int v = (idx < NN) ? g_deg[idx] : 0;
        vals[i] = v;
        s += v;
    }
    ssum[t] = s;
    __syncthreads();
    for (int d = 1; d < SCAN_THREADS; d <<= 1) {
        int v = (t >= d) ? ssum[t - d] : 0;
        __syncthreads();
        ssum[t] += v;
        __syncthreads();
    }
    int excl = ssum[t] - s;
    if (t == SCAN_THREADS - 1) g_bsum[b] = ssum[t];
    int run = excl;
#pragma unroll
    for (int i = 0; i < SCAN_ITEMS; i++) {
        int idx = base + i;
        if (idx < NN) g_off[idx] = run;
        run += vals[i];
    }
}

__global__ void k_scan2() {
    if (threadIdx.x == 0) {
        int run = 0;
        for (int b = 0; b < SCAN_NB; b++) {
            g_boff[b] = run;
            run += g_bsum[b];
        }
        g_off[NN] = run;
    }
}

__global__ void k_scan3() {
    int i = blockIdx.x * blockDim.x + threadIdx.x;
    if (i < NN) {
        int v = g_off[i] + g_boff[i / SCAN_TILE];
        g_off[i] = v;
        g_cursor[i] = v;
    }
}

__global__ void k_scatter(const void* ei) {
    int e = blockIdx.x * blockDim.x + threadIdx.x;
    if (e < NE) {
        int src = load_src(ei, e);
        int dst = load_dst(ei, e);
        int pos = atomicAdd(&g_cursor[dst], 1);
        g_csr[pos] = src;
    }
}

// ---------------- fused 4x linear: q,k,v,skip = x@W + b ---------------------
// Block: 256 threads, 64-row tile, all 128 cols. Per weight matrix:
// W staged in SMEM (64KB), x tile transposed in SMEM (stride 65).
// Thread micro-tile: 4 rows x (4 + 4 split) cols -> 32 fp32 accumulators.
#define LIN_ROWS 64
#define XS 65
#define SMEM_LIN ((C * C + C * XS) * 4)

__global__ void __launch_bounds__(256) k_linear(
    const float* __restrict__ xin_ext, int use_h,
    const float* __restrict__ Wq, const float* __restrict__ bq,
    const float* __restrict__ Wk, const float* __restrict__ bk,
    const float* __restrict__ Wv, const float* __restrict__ bv,
    const float* __restrict__ Ws, const float* __restrict__ bs)
{
    extern __shared__ float sm[];
    float* sW = sm;            // 128*128
    float* sX = sm + C * C;    // 128*XS, transposed: sX[k][row]

    const float* xin = use_h ? g_h : xin_ext;

    int t = threadIdx.x;
    int row0 = blockIdx.x * LIN_ROWS;

    // load x tile transposed (zero-pad past N)
#pragma unroll
    for (int i = 0; i < 8; i++) {
        int lin = t + i * 256;
        int r = lin >> 5;            // 0..63
        int k4 = (lin & 31) * 4;     // 0..124
        float4 xv = make_float4(0.f, 0.f, 0.f, 0.f);
        int gr = row0 + r;
        if (gr < NN) xv = *(const float4*)(xin + (size_t)gr * C + k4);
        sX[(k4 + 0) * XS + r] = xv.x;
        sX[(k4 + 1) * XS + r] = xv.y;
        sX[(k4 + 2) * XS + r] = xv.z;
        sX[(k4 + 3) * XS + r] = xv.w;
    }

    int c0 = (t & 15) * 4;        // cols [c0..c0+3] and [c0+64..c0+67]
    int r0 = (t >> 4) * 4;        // rows [r0..r0+3]

    const float* Wlist[4] = {Wq, Wk, Wv, Ws};
    const float* blist[4] = {bq, bk, bv, bs};
    float* olist[4] = {g_q, g_k, g_v, g_skip};

#pragma unroll
    for (int w = 0; w < 4; w++) {
        __syncthreads();  // prior compute done reading sW (and sX stores visible at w==0)
#pragma unroll
        for (int i = 0; i < 16; i++) {
            int lin = t + i * 256;
            ((float4*)sW)[lin] = ((const float4*)Wlist[w])[lin];
        }
        __syncthreads();

        float acc[4][8];
#pragma unroll
        for (int j = 0; j < 4; j++)
#pragma unroll
            for (int cc = 0; cc < 8; cc++) acc[j][cc] = 0.f;

#pragma unroll 8
        for (int k = 0; k < C; k++) {
            float4 wa = *(const float4*)(sW + k * C + c0);
            float4 wb = *(const float4*)(sW + k * C + c0 + 64);
            float xr[4];
#pragma unroll
            for (int j = 0; j < 4; j++) xr[j] = sX[k * XS + r0 + j];
#pragma unroll
            for (int j = 0; j < 4; j++) {
                acc[j][0] += xr[j] * wa.x;
                acc[j][1] += xr[j] * wa.y;
                acc[j][2] += xr[j] * wa.z;
                acc[j][3] += xr[j] * wa.w;
                acc[j][4] += xr[j] * wb.x;
                acc[j][5] += xr[j] * wb.y;
                acc[j][6] += xr[j] * wb.z;
                acc[j][7] += xr[j] * wb.w;
            }
        }

        float4 ba = *(const float4*)(blist[w] + c0);
        float4 bb = *(const float4*)(blist[w] + c0 + 64);
        float* outp = olist[w];
#pragma unroll
        for (int j = 0; j < 4; j++) {
            int gr = row0 + r0 + j;
            if (gr < NN) {
                float4 oa = make_float4(acc[j][0] + ba.x, acc[j][1] + ba.y,
                                        acc[j][2] + ba.z, acc[j][3] + ba.w);
                float4 ob = make_float4(acc[j][4] + bb.x, acc[j][5] + bb.y,
                                        acc[j][6] + bb.z, acc[j][7] + bb.w);
                *(float4*)(outp + (size_t)gr * C + c0) = oa;
                *(float4*)(outp + (size_t)gr * C + c0 + 64) = ob;
            }
        }
    }
}

// ---------------- per-dst online-softmax aggregation ------------------------
// One warp per destination node. Lane l owns dims [4l..4l+3].
// Streaming softmax: no score storage, no degree bound, no atomics.
__global__ void __launch_bounds__(256) k_agg(float* __restrict__ dout, int layer1)
{
    int warp = (blockIdx.x * blockDim.x + threadIdx.x) >> 5;
    int lane = threadIdx.x & 31;
    if (warp >= NN) return;
    int dst = warp;

    const float scale = 0.08838834764831845f;  // 1/sqrt(128)
    float4 qr = *(const float4*)(g_q + (size_t)dst * C + lane * 4);
    qr.x *= scale; qr.y *= scale; qr.z *= scale; qr.w *= scale;

    int beg = g_off[dst], end = g_off[dst + 1];
    float m = -INFINITY, s = 0.f;
    float4 acc = make_float4(0.f, 0.f, 0.f, 0.f);

    for (int e = beg; e < end; e++) {
        int src = g_csr[e];
        const float* kp = g_k + (size_t)src * C + lane * 4;
        const float* vp = g_v + (size_t)src * C + lane * 4;
        float4 kv = *(const float4*)kp;
        float4 vv = *(const float4*)vp;

        float d = qr.x * kv.x + qr.y * kv.y + qr.z * kv.z + qr.w * kv.w;
#pragma unroll
        for (int o = 16; o > 0; o >>= 1) d += __shfl_xor_sync(0xffffffffu, d, o);

        float nm = fmaxf(m, d);
        float so = __expf(m - nm);   // 0 on first edge (m = -inf)
        float w = __expf(d - nm);
        s = s * so + w;
        acc.x = acc.x * so + w * vv.x;
        acc.y = acc.y * so + w * vv.y;
        acc.z = acc.z * so + w * vv.z;
        acc.w = acc.w * so + w * vv.w;
        m = nm;
    }

    float inv = (s > 0.f) ? (1.f / s) : 0.f;   // deg==0 -> pure skip
    float4 sk = *(const float4*)(g_skip + (size_t)dst * C + lane * 4);
    float4 o = make_float4(sk.x + acc.x * inv, sk.y + acc.y * inv,
                           sk.z + acc.z * inv, sk.w + acc.w * inv);
    float* op;
    if (layer1) {
        o.x = fmaxf(o.x, 0.f); o.y = fmaxf(o.y, 0.f);
        o.z = fmaxf(o.z, 0.f); o.w = fmaxf(o.w, 0.f);
        op = g_h;
    } else {
        op = dout;
    }
    *(float4*)(op + (size_t)dst * C + lane * 4) = o;
}

// ---------------- launch ----------------------------------------------------
extern "C" void kernel_launch(void* const* d_in, const int* in_sizes, int n_in,
                              void* d_out, int out_size)
{
    const float* x = (const float*)d_in[0];
    const void* ei = d_in[1];
    const float* Wq1 = (const float*)d_in[2];  const float* bq1 = (const float*)d_in[3];
    const float* Wk1 = (const float*)d_in[4];  const float* bk1 = (const float*)d_in[5];
    const float* Wv1 = (const float*)d_in[6];  const float* bv1 = (const float*)d_in[7];
    const float* Ws1 = (const float*)d_in[8];  const float* bs1 = (const float*)d_in[9];
    const float* Wq2 = (const float*)d_in[10]; const float* bq2 = (const float*)d_in[11];
    const float* Wk2 = (const float*)d_in[12]; const float* bk2 = (const float*)d_in[13];
    const float* Wv2 = (const float*)d_in[14]; const float* bv2 = (const float*)d_in[15];
    const float* Ws2 = (const float*)d_in[16]; const float* bs2 = (const float*)d_in[17];
    float* out = (float*)d_out;

    cudaFuncSetAttribute(k_linear, cudaFuncAttributeMaxDynamicSharedMemorySize, SMEM_LIN);

    // CSR by destination (edges identical for both layers -> build once)
    k_detect<<<1, 32>>>(ei);
    k_zero_deg<<<(NN + 255) / 256, 256>>>();
    k_hist<<<(NE + 255) / 256, 256>>>(ei);
    k_scan1<<<SCAN_NB, SCAN_THREADS>>>();
    k_scan2<<<1, 32>>>();
    k_scan3<<<(NN + 255) / 256, 256>>>();
    k_scatter<<<(NE + 255) / 256, 256>>>(ei);

    int lin_grid = (NN + LIN_ROWS - 1) / LIN_ROWS;
    int agg_grid = (NN * 32 + 255) / 256;

    // layer 1: q,k,v,skip from x; aggregate + skip + relu -> g_h
    k_linear<<<lin_grid, 256, SMEM_LIN>>>(x, 0, Wq1, bq1, Wk1, bk1, Wv1, bv1, Ws1, bs1);
    k_agg<<<agg_grid, 256>>>(out, 1);

    // layer 2: q,k,v,skip from g_h; aggregate + skip -> out
    k_linear<<<lin_grid, 256, SMEM_LIN>>>(nullptr, 1, Wq2, bq2, Wk2, bk2, Wv2, bv2, Ws2, bs2);
    k_agg<<<agg_grid, 256>>>(out, 0);
}

// round 3
// speedup vs baseline: 1.4434x; 1.4434x over previous
#include <cuda_runtime.h>
#include <cuda_bf16.h>
#include <math.h>
#include <stdint.h>

#define NN 100000
#define NE 800000
#define C 128
#define NTILES 782
#define ROWPAD (NTILES * 128)   // 100096

// ---------------- scratch (device globals; no allocation allowed) ----------
__device__ __nv_bfloat16 g_A[(size_t)ROWPAD * 256];   // [row, hi(128) | lo(128)]
__device__ __nv_bfloat16 g_Wt[8 * 128 * 256];         // [widx][n, hiT(128) | loT(128)]
__device__ float g_q[(size_t)NN * C];
__device__ float g_k[(size_t)NN * C];
__device__ float g_v[(size_t)NN * C];
__device__ float g_skip[(size_t)NN * C];

__device__ int g_deg[NN];
__device__ int g_off[NN + 1];
__device__ int g_cursor[NN];
__device__ int g_csr[NE];
__device__ int g_bsum[64];
__device__ int g_boff[64];
__device__ int g_is64;

// ---------------- helpers ---------------------------------------------------
__device__ __forceinline__ uint32_t smem_to_u32(const void* p) {
    uint32_t a;
    asm("{ .reg .u64 t; cvta.to.shared.u64 t, %1; cvt.u32.u64 %0, t; }" : "=r"(a) : "l"(p));
    return a;
}

__device__ __forceinline__ void ldsm_x4(uint32_t (&r)[4], uint32_t addr) {
    asm volatile("ldmatrix.sync.aligned.m8n8.x4.shared.b16 {%0,%1,%2,%3}, [%4];"
                 : "=r"(r[0]), "=r"(r[1]), "=r"(r[2]), "=r"(r[3]) : "r"(addr));
}

__device__ __forceinline__ void mma16816(float* d, const uint32_t* a, uint32_t b0, uint32_t b1) {
    asm volatile(
        "mma.sync.aligned.m16n8k16.row.col.f32.bf16.bf16.f32 "
        "{%0,%1,%2,%3}, {%4,%5,%6,%7}, {%8,%9}, {%0,%1,%2,%3};"
        : "+f"(d[0]), "+f"(d[1]), "+f"(d[2]), "+f"(d[3])
        : "r"(a[0]), "r"(a[1]), "r"(a[2]), "r"(a[3]), "r"(b0), "r"(b1));
}

// ---------------- edge-index dtype detection -------------------------------
__global__ void k_detect(const void* ei) {
    if (blockIdx.x == 0 && threadIdx.x == 0) {
        const long long* p = (const long long*)ei;
        int ok = 1;
        for (int i = 0; i < 256; i++) {
            long long v = p[i];
            if (v < 0 || v >= NN) { ok = 0; break; }
        }
        g_is64 = ok;
    }
}
__device__ __forceinline__ int load_src(const void* ei, int e) {
    if (g_is64) return (int)((const long long*)ei)[e];
    return ((const int*)ei)[e];
}
__device__ __forceinline__ int load_dst(const void* ei, int e) {
    if (g_is64) return (int)((const long long*)ei)[NE + e];
    return ((const int*)ei)[NE + e];
}

// ---------------- CSR construction -----------------------------------------
__global__ void k_zero_deg() {
    int i = blockIdx.x * blockDim.x + threadIdx.x;
    if (i < NN) g_deg[i] = 0;
}
__global__ void k_hist(const void* ei) {
    int e = blockIdx.x * blockDim.x + threadIdx.x;
    if (e < NE) atomicAdd(&g_deg[load_dst(ei, e)], 1);
}

#define SCAN_ITEMS 8
#define SCAN_THREADS 256
#define SCAN_TILE (SCAN_ITEMS * SCAN_THREADS)
#define SCAN_NB ((NN + SCAN_TILE - 1) / SCAN_TILE)

__global__ void k_scan1() {
    __shared__ int ssum[SCAN_THREADS];
    int b = blockIdx.x, t = threadIdx.x;
    int base = b * SCAN_TILE + t * SCAN_ITEMS;
    int vals[SCAN_ITEMS];
    int s = 0;
#pragma unroll
    for (int i = 0; i < SCAN_ITEMS; i++) {
        int idx = base + i;
        int v = (idx < NN) ? g_deg[idx] : 0;
        vals[i] = v; s += v;
    }
    ssum[t] = s;
    __syncthreads();
    for (int d = 1; d < SCAN_THREADS; d <<= 1) {
        int v = (t >= d) ? ssum[t - d] : 0;
        __syncthreads();
        ssum[t] += v;
        __syncthreads();
    }
    int excl = ssum[t] - s;
    if (t == SCAN_THREADS - 1) g_bsum[b] = ssum[t];
    int run = excl;
#pragma unroll
    for (int i = 0; i < SCAN_ITEMS; i++) {
        int idx = base + i;
        if (idx < NN) g_off[idx] = run;
        run += vals[i];
    }
}
__global__ void k_scan2() {
    if (threadIdx.x == 0) {
        int run = 0;
        for (int b = 0; b < SCAN_NB; b++) { g_boff[b] = run; run += g_bsum[b]; }
        g_off[NN] = run;
    }
}
__global__ void k_scan3() {
    int i = blockIdx.x * blockDim.x + threadIdx.x;
    if (i < NN) {
        int v = g_off[i] + g_boff[i / SCAN_TILE];
        g_off[i] = v;
        g_cursor[i] = v;
    }
}
__global__ void k_scatter(const void* ei) {
    int e = blockIdx.x * blockDim.x + threadIdx.x;
    if (e < NE) {
        int src = load_src(ei, e);
        int dst = load_dst(ei, e);
        int pos = atomicAdd(&g_cursor[dst], 1);
        g_csr[pos] = src;
    }
}

// ---------------- bf16 split converts --------------------------------------
__global__ void k_convx(const float* __restrict__ x) {
    int i = blockIdx.x * blockDim.x + threadIdx.x;
    if (i >= ROWPAD * 32) return;
    int row = i >> 5, d4 = (i & 31) * 4;
    float4 v = make_float4(0.f, 0.f, 0.f, 0.f);
    if (row < NN) v = *(const float4*)(x + (size_t)row * C + d4);
    union { __nv_bfloat16 h[4]; uint2 u; } ph, pl;
    ph.h[0] = __float2bfloat16_rn(v.x);
    ph.h[1] = __float2bfloat16_rn(v.y);
    ph.h[2] = __float2bfloat16_rn(v.z);
    ph.h[3] = __float2bfloat16_rn(v.w);
    pl.h[0] = __float2bfloat16_rn(v.x - __bfloat162float(ph.h[0]));
    pl.h[1] = __float2bfloat16_rn(v.y - __bfloat162float(ph.h[1]));
    pl.h[2] = __float2bfloat16_rn(v.z - __bfloat162float(ph.h[2]));
    pl.h[3] = __float2bfloat16_rn(v.w - __bfloat162float(ph.h[3]));
    *(uint2*)(&g_A[(size_t)row * 256 + d4]) = ph.u;
    *(uint2*)(&g_A[(size_t)row * 256 + 128 + d4]) = pl.u;
}

__global__ void k_convw(const float* W0, const float* W1, const float* W2, const float* W3,
                        const float* W4, const float* W5, const float* W6, const float* W7) {
    int i = blockIdx.x * blockDim.x + threadIdx.x;
    if (i >= 8 * 16384) return;
    int widx = i >> 14;
    int rem = i & 16383;
    int k = rem >> 7, n = rem & 127;
    const float* W = widx == 0 ? W0 : widx == 1 ? W1 : widx == 2 ? W2 : widx == 3 ? W3
                   : widx == 4 ? W4 : widx == 5 ? W5 : widx == 6 ? W6 : W7;
    float v = W[k * 128 + n];
    __nv_bfloat16 hi = __float2bfloat16_rn(v);
    __nv_bfloat16 lo = __float2bfloat16_rn(v - __bfloat162float(hi));
    size_t base = (size_t)widx * 32768 + (size_t)n * 256;
    g_Wt[base + k] = hi;
    g_Wt[base + 128 + k] = lo;
}

// ---------------- mma.sync GEMM: out[tile,128] = A @ WtT + b ----------------
// SMEM: B (weights) 64KB resident; A double-buffered 2x64KB.
// Row layout in SMEM: pitch 512B (256 bf16), 16B chunks swizzled c^(row&7).
#define SMB 0
#define SMA 65536
#define SMTOT 196608

__device__ __forceinline__ void load_A_tile_async(uint32_t sdst, const __nv_bfloat16* gsrc, int tid) {
    const uint4* s4 = (const uint4*)gsrc;
#pragma unroll
    for (int i = 0; i < 16; i++) {
        int id = tid + i * 256;
        int r = id >> 5, c = id & 31;
        uint32_t d = sdst + (uint32_t)r * 512u + (uint32_t)((c ^ (r & 7)) << 4);
        asm volatile("cp.async.cg.shared.global [%0], [%1], 16;\n" :: "r"(d), "l"(s4 + id) : "memory");
    }
    asm volatile("cp.async.commit_group;\n" ::: "memory");
}

__global__ void __launch_bounds__(256) k_gemm(int layer,
    const float* __restrict__ bqp, const float* __restrict__ bkp,
    const float* __restrict__ bvp, const float* __restrict__ bsp)
{
    extern __shared__ char smem[];
    uint32_t sb = smem_to_u32(smem);
    int tid = threadIdx.x;
    int l = tid & 31, w = tid >> 5;
    int widx = blockIdx.y;
    float* outp = widx == 0 ? g_q : widx == 1 ? g_k : widx == 2 ? g_v : g_skip;
    const float* biasp = widx == 0 ? bqp : widx == 1 ? bkp : widx == 2 ? bvp : bsp;

    // B (weights hi|lo, [n][k]) -> swizzled SMEM via cp.async (group 0)
    {
        const uint4* s4 = (const uint4*)(g_Wt + (size_t)(layer * 4 + widx) * 32768);
#pragma unroll
        for (int i = 0; i < 16; i++) {
            int id = tid + i * 256;
            int n = id >> 5, c = id & 31;
            uint32_t d = sb + SMB + (uint32_t)n * 512u + (uint32_t)((c ^ (n & 7)) << 4);
            asm volatile("cp.async.cg.shared.global [%0], [%1], 16;\n" :: "r"(d), "l"(s4 + id) : "memory");
        }
        asm volatile("cp.async.commit_group;\n" ::: "memory");
    }

    int rg = (w & 3) * 32;       // warp row-group within 128-row tile
    int cg = (w >> 2) * 64;      // warp col-group within 128 cols

    // ldmatrix lane addressing
    int rlocA = (l & 7) + ((l >> 3) & 1) * 8;
    int cofsA = (l >> 4) & 1;
    int nlocB = (l & 7) + ((l >> 4) << 3);
    int cofsB = (l >> 3) & 1;
    int rx = l & 7;

    uint32_t addrB[4];
#pragma unroll
    for (int j = 0; j < 4; j++)
        addrB[j] = sb + SMB + (uint32_t)(cg + j * 16 + nlocB) * 512u;

    // bias preload: float2 per n-frag
    float2 biasf[8];
#pragma unroll
    for (int j = 0; j < 8; j++)
        biasf[j] = *(const float2*)(biasp + cg + j * 8 + (l & 3) * 2);

    // prefetch first A tile (group 1)
    int tile0 = blockIdx.x;
    load_A_tile_async(sb + SMA, g_A + (size_t)tile0 * 32768, tid);

    // pass chunk offsets: Ah*Bh, Ah*Bl, Al*Bh  (chunk = 16B = 8 bf16)
    const int APc[3] = {0, 0, 16};
    const int BPc[3] = {0, 16, 0};

    int it = 0;
    for (int tile = tile0; tile < NTILES; tile += gridDim.x, it++) {
        int cur = it & 1;
        __syncthreads();   // everyone done reading the buffer we overwrite next
        int nxt = tile + gridDim.x;
        if (nxt < NTILES) {
            load_A_tile_async(sb + SMA + (cur ^ 1) * 65536u, g_A + (size_t)nxt * 32768, tid);
            asm volatile("cp.async.wait_group 1;\n" ::: "memory");
        } else {
            asm volatile("cp.async.wait_group 0;\n" ::: "memory");
        }
        __syncthreads();

        uint32_t abase = sb + SMA + (uint32_t)cur * 65536u;
        uint32_t addrA0 = abase + (uint32_t)(rg + rlocA) * 512u;
        uint32_t addrA1 = addrA0 + 16u * 512u;

        float acc[2][8][4];
#pragma unroll
        for (int mi = 0; mi < 2; mi++)
#pragma unroll
            for (int ni = 0; ni < 8; ni++)
#pragma unroll
                for (int r = 0; r < 4; r++) acc[mi][ni][r] = 0.f;

#pragma unroll
        for (int p = 0; p < 3; p++) {
#pragma unroll
            for (int s = 0; s < 8; s++) {
                int ca = APc[p] + s * 2;
                int cb = BPc[p] + s * 2;
                uint32_t coffA = (uint32_t)(((ca + cofsA) ^ rx) << 4);
                uint32_t coffB = (uint32_t)(((cb + cofsB) ^ rx) << 4);
                uint32_t Af[2][4];
                ldsm_x4(Af[0], addrA0 + coffA);
                ldsm_x4(Af[1], addrA1 + coffA);
                uint32_t Bf[4][4];
#pragma unroll
                for (int j = 0; j < 4; j++) ldsm_x4(Bf[j], addrB[j] + coffB);
#pragma unroll
                for (int mi = 0; mi < 2; mi++)
#pragma unroll
                    for (int ni = 0; ni < 8; ni++) {
                        uint32_t b0 = Bf[ni >> 1][(ni & 1) * 2 + 0];
                        uint32_t b1 = Bf[ni >> 1][(ni & 1) * 2 + 1];
                        mma16816(acc[mi][ni], Af[mi], b0, b1);
                    }
            }
        }

        // epilogue: bias + direct float2 stores
        int rbase = tile * 128 + rg + (l >> 2);
#pragma unroll
        for (int mi = 0; mi < 2; mi++) {
            int row0 = rbase + mi * 16;
            int row1 = row0 + 8;
#pragma unroll
            for (int ni = 0; ni < 8; ni++) {
                int col = cg + ni * 8 + (l & 3) * 2;
                if (row0 < NN) {
                    float2 v0 = make_float2(acc[mi][ni][0] + biasf[ni].x,
                                            acc[mi][ni][1] + biasf[ni].y);
                    *(float2*)(outp + (size_t)row0 * C + col) = v0;
                }
                if (row1 < NN) {
                    float2 v1 = make_float2(acc[mi][ni][2] + biasf[ni].x,
                                            acc[mi][ni][3] + biasf[ni].y);
                    *(float2*)(outp + (size_t)row1 * C + col) = v1;
                }
            }
        }
    }
}

// ---------------- per-dst online-softmax aggregation ------------------------
__global__ void __launch_bounds__(256) k_agg(float* __restrict__ dout, int layer1)
{
    int warp = (blockIdx.x * blockDim.x + threadIdx.x) >> 5;
    int lane = threadIdx.x & 31;
    if (warp >= NN) return;
    int dst = warp;

    const float scale = 0.08838834764831845f;  // 1/sqrt(128)
    float4 qr = *(const float4*)(g_q + (size_t)dst * C + lane * 4);
    qr.x *= scale; qr.y *= scale; qr.z *= scale; qr.w *= scale;

    int beg = g_off[dst], end = g_off[dst + 1];
    float m = -INFINITY, s = 0.f;
    float4 acc = make_float4(0.f, 0.f, 0.f, 0.f);

    for (int e = beg; e < end; e++) {
        int src = g_csr[e];
        float4 kv = *(const float4*)(g_k + (size_t)src * C + lane * 4);
        float4 vv = *(const float4*)(g_v + (size_t)src * C + lane * 4);

        float d = qr.x * kv.x + qr.y * kv.y + qr.z * kv.z + qr.w * kv.w;
#pragma unroll
        for (int o = 16; o > 0; o >>= 1) d += __shfl_xor_sync(0xffffffffu, d, o);

        float nm = fmaxf(m, d);
        float so = __expf(m - nm);
        float w = __expf(d - nm);
        s = s * so + w;
        acc.x = acc.x * so + w * vv.x;
        acc.y = acc.y * so + w * vv.y;
        acc.z = acc.z * so + w * vv.z;
        acc.w = acc.w * so + w * vv.w;
        m = nm;
    }

    float inv = (s > 0.f) ? (1.f / s) : 0.f;
    float4 sk = *(const float4*)(g_skip + (size_t)dst * C + lane * 4);
    float4 o = make_float4(sk.x + acc.x * inv, sk.y + acc.y * inv,
                           sk.z + acc.z * inv, sk.w + acc.w * inv);
    if (layer1) {
        o.x = fmaxf(o.x, 0.f); o.y = fmaxf(o.y, 0.f);
        o.z = fmaxf(o.z, 0.f); o.w = fmaxf(o.w, 0.f);
        union { __nv_bfloat16 h[4]; uint2 u; } ph, pl;
        ph.h[0] = __float2bfloat16_rn(o.x);
        ph.h[1] = __float2bfloat16_rn(o.y);
        ph.h[2] = __float2bfloat16_rn(o.z);
        ph.h[3] = __float2bfloat16_rn(o.w);
        pl.h[0] = __float2bfloat16_rn(o.x - __bfloat162float(ph.h[0]));
        pl.h[1] = __float2bfloat16_rn(o.y - __bfloat162float(ph.h[1]));
        pl.h[2] = __float2bfloat16_rn(o.z - __bfloat162float(ph.h[2]));
        pl.h[3] = __float2bfloat16_rn(o.w - __bfloat162float(ph.h[3]));
        size_t base = (size_t)dst * 256 + lane * 4;
        *(uint2*)(&g_A[base]) = ph.u;
        *(uint2*)(&g_A[base + 128]) = pl.u;
    } else {
        *(float4*)(dout + (size_t)dst * C + lane * 4) = o;
    }
}

// ---------------- launch ----------------------------------------------------
extern "C" void kernel_launch(void* const* d_in, const int* in_sizes, int n_in,
                              void* d_out, int out_size)
{
    const float* x = (const float*)d_in[0];
    const void* ei = d_in[1];
    const float* Wq1 = (const float*)d_in[2];  const float* bq1 = (const float*)d_in[3];
    const float* Wk1 = (const float*)d_in[4];  const float* bk1 = (const float*)d_in[5];
    const float* Wv1 = (const float*)d_in[6];  const float* bv1 = (const float*)d_in[7];
    const float* Ws1 = (const float*)d_in[8];  const float* bs1 = (const float*)d_in[9];
    const float* Wq2 = (const float*)d_in[10]; const float* bq2 = (const float*)d_in[11];
    const float* Wk2 = (const float*)d_in[12]; const float* bk2 = (const float*)d_in[13];
    const float* Wv2 = (const float*)d_in[14]; const float* bv2 = (const float*)d_in[15];
    const float* Ws2 = (const float*)d_in[16]; const float* bs2 = (const float*)d_in[17];
    float* out = (float*)d_out;

    cudaFuncSetAttribute(k_gemm, cudaFuncAttributeMaxDynamicSharedMemorySize, SMTOT);

    // CSR by destination (edges identical for both layers -> build once)
    k_detect<<<1, 32>>>(ei);
    k_zero_deg<<<(NN + 255) / 256, 256>>>();
    k_hist<<<(NE + 255) / 256, 256>>>(ei);
    k_scan1<<<SCAN_NB, SCAN_THREADS>>>();
    k_scan2<<<1, 32>>>();
    k_scan3<<<(NN + 255) / 256, 256>>>();
    k_scatter<<<(NE + 255) / 256, 256>>>(ei);

    // operand converts
    k_convx<<<(ROWPAD * 32 + 255) / 256, 256>>>(x);
    k_convw<<<(8 * 16384 + 255) / 256, 256>>>(Wq1, Wk1, Wv1, Ws1, Wq2, Wk2, Wv2, Ws2);

    dim3 gg(37, 4);
    int agg_grid = (NN * 32 + 255) / 256;

    // layer 1
    k_gemm<<<gg, 256, SMTOT>>>(0, bq1, bk1, bv1, bs1);
    k_agg<<<agg_grid, 256>>>(out, 1);   // writes layer-2 A (bf16 split)

    // layer 2
    k_gemm<<<gg, 256, SMTOT>>>(1, bq2, bk2, bv2, bs2);
    k_agg<<<agg_grid, 256>>>(out, 0);
}